// round 5
// baseline (speedup 1.0000x reference)
#include <cuda_runtime.h>
#include <cuda_bf16.h>
#include <cstdint>
#include <math.h>

// ---------------- scratch (device globals; no allocations) ----------------
__device__ float g_h1[131072000];   // 16*512*16000
__device__ float g_h2[32768000];    // 16*512*4000
__device__ float g_h3[16384000];    // 16*512*2000
__device__ float g_h4[8192000];     // 16*512*1000
__device__ float g_h5[4096000];     // 16*512*500
__device__ float g_zbn[4096000];    // [t*16+b][512]
__device__ float g_scale[5*512];
__device__ float g_shift[5*512];
__device__ float g_wiht[393216];    // [d*768 + j]
__device__ float g_gi[6144000];     // [(t*16+b)*768 + j]
__device__ float g_enc[98304];      // [(k*16+b)*512 + d]
__device__ float g_ct[4096];
__device__ float g_hlast[4096];
__device__ float g_pred[98304];
__device__ float g_total[3072];

// bf16 hi/lo split weights: [co][ci*K+k] (native flatten of input layout)
__device__ __nv_bfloat16 g_w2h[2097152],  g_w2l[2097152];    // 512*4096
__device__ __nv_bfloat16 g_w345h[3145728], g_w345l[3145728]; // 3*512*2048

// phase-split BN'd inputs, bf16 hi/lo: [b][ci][p][W]
__device__ __nv_bfloat16 g_xph2[132186112], g_xpl2[132186112]; // W=4034, S=4
__device__ __nv_bfloat16 g_xph3[33587200],  g_xpl3[33587200];  // W=2050, S=2
__device__ __nv_bfloat16 g_xph4[16809984],  g_xpl4[16809984];  // W=1026
__device__ __nv_bfloat16 g_xph5[8421376],   g_xpl5[8421376];   // W=514

// ---------------- weight split (identity layout) ----------------
__global__ void wsplit_kernel(const float* __restrict__ w,
                              __nv_bfloat16* __restrict__ hi,
                              __nv_bfloat16* __restrict__ lo, int n) {
    int id = blockIdx.x*256 + threadIdx.x;
    if (id >= n) return;
    float v = w[id];
    __nv_bfloat16 h = __float2bfloat16(v);
    hi[id] = h;
    lo[id] = __float2bfloat16(v - __bfloat162float(h));
}
__global__ void tr_wih_kernel(const float* __restrict__ w) {
    int id = blockIdx.x*256 + threadIdx.x;
    if (id >= 512*768) return;
    int d = id / 768;
    int j = id - d*768;
    g_wiht[id] = w[(long)j*512 + d];
}

// ---------------- conv1: Cin=1, K=10, S=5, pad=3, T=16000 ----------------
__global__ void __launch_bounds__(256) conv1_kernel(
    const float* __restrict__ x, const float* __restrict__ w1, float* __restrict__ out)
{
    __shared__ float xs[656];
    __shared__ float ws[640];
    const int b = blockIdx.z, co0 = blockIdx.y*64, t0 = blockIdx.x*128;
    const int tid = threadIdx.x;
    const int base = 5*t0 - 3;
    const float* xb = x + (long)b*80000;
    for (int i = tid; i < 645; i += 256) {
        int p = base + i;
        xs[i] = (p >= 0 && p < 80000) ? xb[p] : 0.f;
    }
    for (int i = tid; i < 640; i += 256) ws[i] = w1[co0*10 + i];
    __syncthreads();
    for (int i = tid; i < 64*128; i += 256) {
        int co_l = i >> 7, t_l = i & 127;
        float a = 0.f;
        #pragma unroll
        for (int k = 0; k < 10; k++) a = fmaf(ws[co_l*10+k], xs[5*t_l+k], a);
        out[((long)b*512 + co0 + co_l)*16000 + t0 + t_l] = a;
    }
}

// ---------------- BN stats: one block per channel ----------------
__global__ void __launch_bounds__(256) stats_kernel(
    const float* __restrict__ h, int T, int l,
    const float* __restrict__ gamma, const float* __restrict__ beta)
{
    int c = blockIdx.x;
    int tid = threadIdx.x;
    float s = 0.f, s2 = 0.f;
    for (int b = 0; b < 16; b++) {
        const float* p = h + ((long)b*512 + c)*T;
        for (int i = tid; i < T; i += 256) { float v = p[i]; s += v; s2 = fmaf(v, v, s2); }
    }
    __shared__ double sh[256], sh2[256];
    sh[tid] = (double)s; sh2[tid] = (double)s2;
    __syncthreads();
    for (int st = 128; st > 0; st >>= 1) {
        if (tid < st) { sh[tid] += sh[tid+st]; sh2[tid] += sh2[tid+st]; }
        __syncthreads();
    }
    if (tid == 0) {
        double N = 16.0 * (double)T;
        double m = sh[0] / N;
        double var = sh2[0] / N - m*m;
        double sc = (double)gamma[l*512+c] / sqrt(var + 1e-5);
        g_scale[l*512+c] = (float)sc;
        g_shift[l*512+c] = (float)((double)beta[l*512+c] - m*sc);
    }
}

// ---------------- prep: BN+relu, phase-split, bf16 hi/lo ----------------
// xp[b][ci][p][ui], pos = S*(ui-1)+p, zero outside [0,Tin)
template<int S>
__global__ void prep_kernel(const float* __restrict__ h, int Tin, int W, int l,
                            __nv_bfloat16* __restrict__ xh, __nv_bfloat16* __restrict__ xl)
{
    long id = (long)blockIdx.x*256 + threadIdx.x;
    long total = (long)16*512*S*W;
    if (id >= total) return;
    int ui = (int)(id % W);
    long q = id / W;
    int p = (int)(q % S); q /= S;
    int ci = (int)(q & 511);
    int b = (int)(q >> 9);
    int pos = S*(ui-1) + p;
    float v = 0.f;
    if (pos >= 0 && pos < Tin) {
        float raw = h[((long)b*512 + ci)*Tin + pos];
        v = fmaxf(0.f, fmaf(raw, g_scale[l*512+ci], g_shift[l*512+ci]));
    }
    __nv_bfloat16 hi = __float2bfloat16(v);
    xh[id] = hi;
    xl[id] = __float2bfloat16(v - __bfloat162float(hi));
}

// ---------------- tensor-core conv: bf16x3 implicit GEMM ----------------
__device__ __forceinline__ unsigned scvt(const void* p) {
    return (unsigned)__cvta_generic_to_shared(p);
}
__device__ __forceinline__ void ldsm_x4(unsigned addr, unsigned& r0, unsigned& r1,
                                        unsigned& r2, unsigned& r3) {
    asm volatile("ldmatrix.sync.aligned.m8n8.x4.shared.b16 {%0,%1,%2,%3}, [%4];"
                 : "=r"(r0), "=r"(r1), "=r"(r2), "=r"(r3) : "r"(addr));
}
__device__ __forceinline__ void ldsm_x2(unsigned addr, unsigned& r0, unsigned& r1) {
    asm volatile("ldmatrix.sync.aligned.m8n8.x2.shared.b16 {%0,%1}, [%2];"
                 : "=r"(r0), "=r"(r1) : "r"(addr));
}
__device__ __forceinline__ void mma_bf16(float* c, const unsigned* a, const unsigned* b) {
    asm volatile("mma.sync.aligned.m16n8k16.row.col.f32.bf16.bf16.f32 "
                 "{%0,%1,%2,%3},{%4,%5,%6,%7},{%8,%9},{%0,%1,%2,%3};"
                 : "+f"(c[0]), "+f"(c[1]), "+f"(c[2]), "+f"(c[3])
                 : "r"(a[0]), "r"(a[1]), "r"(a[2]), "r"(a[3]), "r"(b[0]), "r"(b[1]));
}

// C[co][t] = sum_{ci,k} W[co][ci*K+k] * xp[ci][p(k)][t+e(k)+1]
// block: 128 co x 64 t; 8 warps (4M x 2N); warp: 32x32; k-chunk 32
template<int K, int LK, int S, int LS, int PAD>
__global__ void __launch_bounds__(256) convmma_kernel(
    const __nv_bfloat16* __restrict__ xph, const __nv_bfloat16* __restrict__ xpl,
    const __nv_bfloat16* __restrict__ wh,  const __nv_bfloat16* __restrict__ wl,
    float* __restrict__ out, int Tout, int W)
{
    constexpr int KK = 512*K;
    __shared__ __nv_bfloat16 Ash[128*40];
    __shared__ __nv_bfloat16 Asl[128*40];
    __shared__ __nv_bfloat16 Bsh[64*40];
    __shared__ __nv_bfloat16 Bsl[64*40];
    const int b = blockIdx.z, co0 = blockIdx.y*128, t0 = blockIdx.x*64;
    const int tid = threadIdx.x;
    const int lane = tid & 31, warp = tid >> 5;
    const int wm = (warp & 3)*32, wn = (warp >> 2)*32;
    float acc[2][4][4];
    #pragma unroll
    for (int mt = 0; mt < 2; mt++)
        #pragma unroll
        for (int nt = 0; nt < 4; nt++)
            #pragma unroll
            for (int i = 0; i < 4; i++) acc[mt][nt][i] = 0.f;

    const long xci = (long)S*W;
    const long xbase = (long)b*512*xci;
    const int coA = tid & 127, segA = tid >> 7;   // A staging
    const int kkB = tid >> 3,  tp   = tid & 7;    // B staging

    for (int kk0 = 0; kk0 < KK; kk0 += 32) {
        __syncthreads();
        {   // stage A: 128 rows x 32 halves (hi & lo)
            const __nv_bfloat16* s1 = wh + (long)(co0+coA)*KK + kk0 + segA*16;
            const __nv_bfloat16* s2 = wl + (long)(co0+coA)*KK + kk0 + segA*16;
            *(uint4*)(Ash + coA*40 + segA*16)     = *(const uint4*)s1;
            *(uint4*)(Ash + coA*40 + segA*16 + 8) = *(const uint4*)(s1 + 8);
            *(uint4*)(Asl + coA*40 + segA*16)     = *(const uint4*)s2;
            *(uint4*)(Asl + coA*40 + segA*16 + 8) = *(const uint4*)(s2 + 8);
        }
        {   // stage B: 64 t x 32 kk (hi & lo)
            int kkg = kk0 + kkB;
            int ci = kkg >> LK, k = kkg & (K-1);
            int e = (k - PAD) >> LS, p = (k - PAD) & (S-1);
            const __nv_bfloat16* r1 = xph + xbase + (long)ci*xci + (long)p*W + (t0 + e + 1);
            const __nv_bfloat16* r2 = xpl + xbase + (long)ci*xci + (long)p*W + (t0 + e + 1);
            #pragma unroll
            for (int j = 0; j < 8; j++) {
                int t = tp*8 + j;
                Bsh[t*40 + kkB] = r1[t];
                Bsl[t*40 + kkB] = r2[t];
            }
        }
        __syncthreads();
        #pragma unroll
        for (int k16 = 0; k16 < 2; k16++) {
            unsigned ah[2][4], al[2][4], bh[4][2], bl[4][2];
            #pragma unroll
            for (int mt = 0; mt < 2; mt++) {
                int row = wm + mt*16 + (lane & 15);
                unsigned off = (unsigned)(row*40 + k16*16 + (lane >> 4)*8)*2u;
                ldsm_x4(scvt(Ash) + off, ah[mt][0], ah[mt][1], ah[mt][2], ah[mt][3]);
                ldsm_x4(scvt(Asl) + off, al[mt][0], al[mt][1], al[mt][2], al[mt][3]);
            }
            #pragma unroll
            for (int nt = 0; nt < 4; nt++) {
                int rowb = wn + nt*8 + (lane & 7);
                unsigned off = (unsigned)(rowb*40 + k16*16 + ((lane >> 3) & 1)*8)*2u;
                ldsm_x2(scvt(Bsh) + off, bh[nt][0], bh[nt][1]);
                ldsm_x2(scvt(Bsl) + off, bl[nt][0], bl[nt][1]);
            }
            #pragma unroll
            for (int mt = 0; mt < 2; mt++)
                #pragma unroll
                for (int nt = 0; nt < 4; nt++) {
                    mma_bf16(acc[mt][nt], ah[mt], bh[nt]);
                    mma_bf16(acc[mt][nt], ah[mt], bl[nt]);
                    mma_bf16(acc[mt][nt], al[mt], bh[nt]);
                }
        }
    }
    // epilogue
    const int g2 = lane >> 2, tq = lane & 3;
    #pragma unroll
    for (int mt = 0; mt < 2; mt++) {
        #pragma unroll
        for (int nt = 0; nt < 4; nt++) {
            int col = t0 + wn + nt*8 + tq*2;
            if (col < Tout) {
                int row = co0 + wm + mt*16 + g2;
                float2 v0; v0.x = acc[mt][nt][0]; v0.y = acc[mt][nt][1];
                *(float2*)(out + ((long)b*512 + row)*Tout + col) = v0;
                float2 v1; v1.x = acc[mt][nt][2]; v1.y = acc[mt][nt][3];
                *(float2*)(out + ((long)b*512 + row + 8)*Tout + col) = v1;
            }
        }
    }
}

// ---------------- zbn: BN5+relu, transpose to [t][b][d] ----------------
__global__ void zbn_kernel(const float* __restrict__ h5) {
    int t = blockIdx.x, b = blockIdx.y, d = threadIdx.x;
    float raw = h5[((long)b*512 + d)*500 + t];
    float v = fmaxf(0.f, fmaf(raw, g_scale[4*512+d], g_shift[4*512+d]));
    g_zbn[((long)t*16 + b)*512 + d] = v;
}

__global__ void enc_kernel(const int* __restrict__ ts) {
    int k = blockIdx.x, b = blockIdx.y, d = threadIdx.x;
    int t = ts[b] + k + 1;
    g_enc[((long)(k*16) + b)*512 + d] = g_zbn[((long)t*16 + b)*512 + d];
}

// ---------------- gi GEMM: [8000 x 512] @ [512 x 768] + bih ----------------
__global__ void __launch_bounds__(256) gi_kernel(const float* __restrict__ bih) {
    __shared__ float as[128*17];
    __shared__ float bs[16*64];
    const int r0 = blockIdx.x*128, c0 = blockIdx.y*64;
    const int tid = threadIdx.x;
    const int cx = tid & 15;
    const int ry = tid >> 4;
    float acc[8][4];
    #pragma unroll
    for (int i = 0; i < 8; i++)
        #pragma unroll
        for (int j = 0; j < 4; j++) acc[i][j] = 0.f;
    for (int d0 = 0; d0 < 512; d0 += 16) {
        __syncthreads();
        for (int i = tid; i < 2048; i += 256) {
            int row = i >> 4, dd = i & 15;
            int rg = r0 + row;
            as[row*17 + dd] = (rg < 8000) ? g_zbn[(long)rg*512 + d0 + dd] : 0.f;
        }
        for (int i = tid; i < 1024; i += 256) {
            int dd = i >> 6, col = i & 63;
            bs[i] = g_wiht[(long)(d0+dd)*768 + c0 + col];
        }
        __syncthreads();
        #pragma unroll
        for (int dd = 0; dd < 16; dd++) {
            float4 b4 = *(const float4*)(bs + dd*64 + cx*4);
            float bv[4] = {b4.x, b4.y, b4.z, b4.w};
            #pragma unroll
            for (int ii = 0; ii < 8; ii++) {
                float av = as[(ry + 16*ii)*17 + dd];
                #pragma unroll
                for (int j = 0; j < 4; j++) acc[ii][j] = fmaf(av, bv[j], acc[ii][j]);
            }
        }
    }
    #pragma unroll
    for (int ii = 0; ii < 8; ii++) {
        int rg = r0 + ry + 16*ii;
        if (rg < 8000) {
            #pragma unroll
            for (int j = 0; j < 4; j++)
                g_gi[(long)rg*768 + c0 + cx*4 + j] = acc[ii][j] + bih[c0 + cx*4 + j];
        }
    }
}

// ---------------- GRU: persistent, 1 block/batch, 1024 threads ----------
__global__ void __launch_bounds__(1024) gru_kernel(
    const float* __restrict__ hidden, const int* __restrict__ ts,
    const float* __restrict__ whh, const float* __restrict__ bhh,
    const float* __restrict__ bih)
{
    const int b = blockIdx.x;
    const int tid = threadIdx.x;
    const int w = tid >> 5, lane = tid & 31;
    const int g = lane >> 3, l = lane & 7;
    __shared__ float h_s[256];
    __shared__ float gh_s[768];
    if (tid < 256) h_s[tid] = hidden[b*256 + tid];
    const int tsb = ts[b];
    for (int t = 0; t < 500; t++) {
        __syncthreads();
        float hv[32];
        #pragma unroll
        for (int i = 0; i < 8; i++) {
            float4 h4 = *(const float4*)(h_s + l*32 + i*4);
            hv[i*4+0]=h4.x; hv[i*4+1]=h4.y; hv[i*4+2]=h4.z; hv[i*4+3]=h4.w;
        }
        #pragma unroll
        for (int it = 0; it < 6; it++) {
            int row = w*24 + it*4 + g;
            const float4* wp = (const float4*)(whh + (long)row*256 + l*32);
            float a = 0.f;
            #pragma unroll
            for (int i = 0; i < 8; i++) {
                float4 w4 = wp[i];
                a = fmaf(w4.x, hv[i*4+0], a);
                a = fmaf(w4.y, hv[i*4+1], a);
                a = fmaf(w4.z, hv[i*4+2], a);
                a = fmaf(w4.w, hv[i*4+3], a);
            }
            a += __shfl_down_sync(0xffffffffu, a, 4, 8);
            a += __shfl_down_sync(0xffffffffu, a, 2, 8);
            a += __shfl_down_sync(0xffffffffu, a, 1, 8);
            if (l == 0) gh_s[row] = a + bhh[row];
        }
        __syncthreads();
        if (tid < 256) {
            bool masked = (t > tsb);
            const float* gp = g_gi + ((long)t*16 + b)*768;
            float gr = masked ? bih[tid]     : gp[tid];
            float gz = masked ? bih[256+tid] : gp[256+tid];
            float gn = masked ? bih[512+tid] : gp[512+tid];
            float r = 1.f/(1.f + expf(-(gr + gh_s[tid])));
            float z = 1.f/(1.f + expf(-(gz + gh_s[256+tid])));
            float n = tanhf(gn + r*gh_s[512+tid]);
            float hn = (1.f - z)*n + z*h_s[tid];
            h_s[tid] = hn;
            if (t == tsb) g_ct[b*256+tid] = hn;
            if (t == 499) g_hlast[b*256+tid] = hn;
        }
    }
}

// ---------------- pred: [16x256] x Wk_w[k][512][256] ----------------
__global__ void __launch_bounds__(128) pred_kernel(
    const float* __restrict__ wkw, const float* __restrict__ wkb)
{
    const int k = blockIdx.x, d0 = blockIdx.y*128;
    const int tid = threadIdx.x;
    __shared__ float ct_s[16*256];
    __shared__ float wt_s[128*33];
    for (int i = tid; i < 4096; i += 128) ct_s[i] = g_ct[i];
    float acc[16];
    #pragma unroll
    for (int bb = 0; bb < 16; bb++) acc[bb] = 0.f;
    for (int h0 = 0; h0 < 256; h0 += 32) {
        __syncthreads();
        for (int i = tid; i < 4096; i += 128) {
            int row = i >> 5, hh = i & 31;
            wt_s[row*33 + hh] = wkw[((long)k*512 + d0 + row)*256 + h0 + hh];
        }
        __syncthreads();
        #pragma unroll
        for (int hh = 0; hh < 32; hh++) {
            float wv = wt_s[tid*33 + hh];
            #pragma unroll
            for (int bb = 0; bb < 16; bb++)
                acc[bb] = fmaf(wv, ct_s[bb*256 + h0 + hh], acc[bb]);
        }
    }
    for (int bb = 0; bb < 16; bb++)
        g_pred[((long)(k*16) + bb)*512 + d0 + tid] = acc[bb] + wkb[k*512 + d0 + tid];
}

// ---------------- total[k][b][c] = enc[k][b] . pred[k][c] ----------------
__global__ void __launch_bounds__(256) total_kernel() {
    const int k = blockIdx.x, tid = threadIdx.x;
    const int b = tid >> 4, c = tid & 15;
    const float* ep = g_enc + ((long)(k*16) + b)*512;
    const float* pp = g_pred + ((long)(k*16) + c)*512;
    float a = 0.f;
    for (int d = 0; d < 512; d++) a = fmaf(ep[d], pp[d], a);
    g_total[(k*16+b)*16 + c] = a;
}

// ---------------- final: nce, accuracy, copy h_last ----------------
__global__ void final_kernel(float* __restrict__ out) {
    const int tid = threadIdx.x;
    for (int i = tid; i < 4096; i += 256) out[2+i] = g_hlast[i];
    if (tid == 0) {
        double nce = 0.0;
        for (int k = 0; k < 12; k++) {
            for (int b = 0; b < 16; b++) {
                const float* row = g_total + (k*16+b)*16;
                float m = row[0];
                for (int c = 1; c < 16; c++) m = fmaxf(m, row[c]);
                double s = 0.0;
                for (int c = 0; c < 16; c++) s += exp((double)row[c] - (double)m);
                nce += (double)row[b] - ((double)m + log(s));
            }
        }
        out[1] = (float)(nce / (-16.0 * 12.0));
        double lseb[16];
        for (int b = 0; b < 16; b++) {
            const float* row = g_total + (11*16+b)*16;
            float m = row[0];
            for (int c = 1; c < 16; c++) m = fmaxf(m, row[c]);
            double s = 0.0;
            for (int c = 0; c < 16; c++) s += exp((double)row[c] - (double)m);
            lseb[b] = (double)m + log(s);
        }
        int correct = 0;
        for (int c = 0; c < 16; c++) {
            double best = -1e300; int bb = -1;
            for (int b = 0; b < 16; b++) {
                double v = (double)g_total[(11*16+b)*16 + c] - lseb[b];
                if (v > best) { best = v; bb = b; }
            }
            if (bb == c) correct++;
        }
        out[0] = (float)correct / 16.0f;
    }
}

// ---------------- host ----------------
extern "C" void kernel_launch(void* const* d_in, const int* in_sizes, int n_in,
                              void* d_out, int out_size) {
    const float* x      = (const float*)d_in[0];
    const float* hidden = (const float*)d_in[1];
    const int*   ts     = (const int*)  d_in[3];
    const float* w1     = (const float*)d_in[4];
    const float* w2     = (const float*)d_in[5];
    const float* w345   = (const float*)d_in[6];
    const float* gamma  = (const float*)d_in[7];
    const float* beta   = (const float*)d_in[8];
    const float* wih    = (const float*)d_in[9];
    const float* whh    = (const float*)d_in[10];
    const float* bih    = (const float*)d_in[11];
    const float* bhh    = (const float*)d_in[12];
    const float* wkw    = (const float*)d_in[13];
    const float* wkb    = (const float*)d_in[14];
    float* out = (float*)d_out;

    float *h1, *h2, *h3, *h4, *h5;
    cudaGetSymbolAddress((void**)&h1, g_h1);
    cudaGetSymbolAddress((void**)&h2, g_h2);
    cudaGetSymbolAddress((void**)&h3, g_h3);
    cudaGetSymbolAddress((void**)&h4, g_h4);
    cudaGetSymbolAddress((void**)&h5, g_h5);
    __nv_bfloat16 *w2h, *w2l, *w345h, *w345l;
    cudaGetSymbolAddress((void**)&w2h, g_w2h);
    cudaGetSymbolAddress((void**)&w2l, g_w2l);
    cudaGetSymbolAddress((void**)&w345h, g_w345h);
    cudaGetSymbolAddress((void**)&w345l, g_w345l);
    __nv_bfloat16 *xph2,*xpl2,*xph3,*xpl3,*xph4,*xpl4,*xph5,*xpl5;
    cudaGetSymbolAddress((void**)&xph2, g_xph2);
    cudaGetSymbolAddress((void**)&xpl2, g_xpl2);
    cudaGetSymbolAddress((void**)&xph3, g_xph3);
    cudaGetSymbolAddress((void**)&xpl3, g_xpl3);
    cudaGetSymbolAddress((void**)&xph4, g_xph4);
    cudaGetSymbolAddress((void**)&xpl4, g_xpl4);
    cudaGetSymbolAddress((void**)&xph5, g_xph5);
    cudaGetSymbolAddress((void**)&xpl5, g_xpl5);

    wsplit_kernel<<<8192, 256>>>(w2, w2h, w2l, 2097152);
    wsplit_kernel<<<12288, 256>>>(w345, w345h, w345l, 3145728);
    tr_wih_kernel<<<1536, 256>>>(wih);

    conv1_kernel<<<dim3(125, 8, 16), 256>>>(x, w1, h1);
    stats_kernel<<<512, 256>>>(h1, 16000, 0, gamma, beta);

    // layer 2: S=4, pad=2, K=8, Tout=4000, 63 t-tiles, W=4034
    prep_kernel<4><<<(int)((16L*512*4*4034 + 255)/256), 256>>>(h1, 16000, 4034, 0, xph2, xpl2);
    convmma_kernel<8,3,4,2,2><<<dim3(63, 4, 16), 256>>>(xph2, xpl2, w2h, w2l, h2, 4000, 4034);
    stats_kernel<<<512, 256>>>(h2, 4000, 1, gamma, beta);

    // layer 3: S=2, pad=1, K=4, Tout=2000, 32 tiles, W=2050
    prep_kernel<2><<<(int)((16L*512*2*2050 + 255)/256), 256>>>(h2, 4000, 2050, 1, xph3, xpl3);
    convmma_kernel<4,2,2,1,1><<<dim3(32, 4, 16), 256>>>(xph3, xpl3, w345h, w345l, h3, 2000, 2050);
    stats_kernel<<<512, 256>>>(h3, 2000, 2, gamma, beta);

    // layer 4: Tout=1000, 16 tiles, W=1026
    prep_kernel<2><<<(int)((16L*512*2*1026 + 255)/256), 256>>>(h3, 2000, 1026, 2, xph4, xpl4);
    convmma_kernel<4,2,2,1,1><<<dim3(16, 4, 16), 256>>>(xph4, xpl4, w345h + 1048576, w345l + 1048576, h4, 1000, 1026);
    stats_kernel<<<512, 256>>>(h4, 1000, 3, gamma, beta);

    // layer 5: Tout=500, 8 tiles, W=514
    prep_kernel<2><<<(int)((16L*512*2*514 + 255)/256), 256>>>(h4, 1000, 514, 3, xph5, xpl5);
    convmma_kernel<4,2,2,1,1><<<dim3(8, 4, 16), 256>>>(xph5, xpl5, w345h + 2097152, w345l + 2097152, h5, 500, 514);
    stats_kernel<<<512, 256>>>(h5, 500, 4, gamma, beta);

    zbn_kernel<<<dim3(500, 16), 512>>>(h5);
    enc_kernel<<<dim3(12, 16), 512>>>(ts);
    gi_kernel<<<dim3(63, 12), 256>>>(bih);
    gru_kernel<<<16, 1024>>>(hidden, ts, whh, bhh, bih);
    pred_kernel<<<dim3(12, 4), 128>>>(wkw, wkb);
    total_kernel<<<12, 256>>>();
    final_kernel<<<1, 256>>>(out);
}